// round 14
// baseline (speedup 1.0000x reference)
#include <cuda_runtime.h>
#include <cstdint>

#define BB 32
#define TT_ 256
#define CHL 16
#define CE_ 64
#define HC_ 64
#define HW_ 256
#define EMB_ 300
#define EIN_ 428
#define XS_ 432
#define LL_ 32
#define CV_ 128
#define NROW (BB*TT_)

typedef unsigned long long ull;

__device__ float g_x[NROW*XS_];
__device__ float g_xg[2][NROW*1024];          // natural: [dir][m][gate]
__device__ float g_ctab[2][CV_*256];          // char input-projection table
__device__ float g_hs[NROW*512];              // [row][dir*256+k]  (for proj)
__device__ float g_feats[NROW*LL_];

__device__ __forceinline__ float sigf(float x) { return 1.0f/(1.0f+__expf(-x)); }
__device__ __forceinline__ float tanh_(float x) {
    x = fmaxf(x, -43.0f);
    float e = __expf(-2.0f*x);
    return (1.0f - e)/(1.0f + e);
}

// ---- packed f32x2 helpers (sm_100+) ----
__device__ __forceinline__ ull fma2(ull a, ull b, ull c) {
    ull d;
    asm("fma.rn.f32x2 %0, %1, %2, %3;" : "=l"(d) : "l"(a), "l"(b), "l"(c));
    return d;
}
__device__ __forceinline__ ull dup2(float x) {
    ull d;
    asm("mov.b64 %0, {%1, %1};" : "=l"(d) : "f"(x));
    return d;
}
__device__ __forceinline__ float2 unpack2(ull v) {
    float2 r;
    asm("mov.b64 {%0, %1}, %2;" : "=f"(r.x), "=f"(r.y) : "l"(v));
    return r;
}
__device__ __forceinline__ float hsum2(ull v) {
    float2 r = unpack2(v);
    return r.x + r.y;
}
__device__ __forceinline__ ull pack2(float lo, float hi) {
    ull d;
    asm("mov.b64 %0, {%1, %2};" : "=l"(d) : "f"(lo), "f"(hi));
    return d;
}

__device__ __forceinline__ uint32_t smem_u32(const void* p) {
    uint32_t a;
    asm("{ .reg .u64 t; cvta.to.shared.u64 t, %1; cvt.u32.u64 %0, t; }"
        : "=r"(a) : "l"(p));
    return a;
}
#define CLUSTER_SYNC() do { \
    asm volatile("barrier.cluster.arrive.aligned;" ::: "memory"); \
    asm volatile("barrier.cluster.wait.aligned;" ::: "memory"); \
} while(0)

__device__ __forceinline__ void mbar_init(uint32_t addr, uint32_t cnt) {
    asm volatile("mbarrier.init.shared.b64 [%0], %1;" :: "r"(addr), "r"(cnt) : "memory");
}
__device__ __forceinline__ void mbar_expect_tx(uint32_t addr, uint32_t bytes) {
    asm volatile("mbarrier.arrive.expect_tx.shared.b64 _, [%0], %1;"
                 :: "r"(addr), "r"(bytes) : "memory");
}
__device__ __forceinline__ void mbar_wait(uint32_t addr, uint32_t parity) {
    asm volatile(
        "{\n\t.reg .pred P;\n\t"
        "W_%=:\n\t"
        "mbarrier.try_wait.parity.acquire.cta.shared::cta.b64 P, [%0], %1, 0x989680;\n\t"
        "@P bra D_%=;\n\t"
        "bra W_%=;\n\t"
        "D_%=:\n\t}"
        :: "r"(addr), "r"(parity) : "memory");
}

// ---- ctab[dir][c][g] = char_emb[c] . Wih[g] ----
__global__ void ctab_kernel(const float* __restrict__ char_emb,
                            const float* __restrict__ Wf,
                            const float* __restrict__ Wb)
{
    __shared__ float e[64];
    const int c = blockIdx.x, dir = blockIdx.y;
    const float* W = dir ? Wb : Wf;
    const int g = threadIdx.x;
    if (g < 64) e[g] = char_emb[c*64 + g];
    __syncthreads();
    float s = 0.f;
    #pragma unroll
    for (int k = 0; k < 64; ++k) s += e[k]*W[g*64 + k];
    g_ctab[dir][c*256 + g] = s;
}

// ---- char recurrence + x assembly: 8 seqs/block, dir = blockIdx.y, f32x2 ----
__global__ void char_rec_kernel(
    const float* __restrict__ Whh_f, const float* __restrict__ bih_f, const float* __restrict__ bhh_f,
    const float* __restrict__ Whh_b, const float* __restrict__ bih_b, const float* __restrict__ bhh_b,
    const int* __restrict__ cseq,
    const int* __restrict__ sentence, const float* __restrict__ emb)
{
    extern __shared__ __align__(16) unsigned char smraw[];
    const int P = 257;
    ull*   WhhP = (ull*)smraw;                 // [32 k2][257]
    float* bsum = (float*)(WhhP + 32*P);       // [256]
    float* hsm  = bsum + 256;                  // [8][64]
    float* csm  = hsm + 512;                   // [8][64]
    float* gts  = csm + 512;                   // [8][256]
    __shared__ int cid[128];

    const int dir = blockIdx.y;
    const float* Whh = dir ? Whh_b : Whh_f;
    const float* bih = dir ? bih_b : bih_f;
    const float* bhh = dir ? bhh_b : bhh_f;
    const float* tab = g_ctab[dir];
    const int tid = threadIdx.x;
    const int seq0 = blockIdx.x*8;

    const ull* Wp = (const ull*)Whh;           // [256][32]
    for (int u = tid; u < 256*32; u += 256) {
        int g = u >> 5, k2 = u & 31;
        WhhP[k2*P + g] = Wp[u];
    }
    bsum[tid] = bih[tid] + bhh[tid];
    if (tid < 128) cid[tid] = cseq[seq0*CHL + tid];
    for (int u = tid; u < 512; u += 256) { hsm[u] = 0.f; csm[u] = 0.f; }
    __syncthreads();

    const int g = tid;
    for (int step = 0; step < 16; ++step) {
        int tcur = dir ? (15 - step) : step;
        ull acc[8];
        #pragma unroll
        for (int s = 0; s < 8; ++s)
            acc[s] = pack2(bsum[g] + tab[cid[s*16 + tcur]*256 + g], 0.f);
        #pragma unroll 4
        for (int k4 = 0; k4 < 16; ++k4) {
            ull wa = WhhP[(2*k4)*P + g];
            ull wb = WhhP[(2*k4+1)*P + g];
            #pragma unroll
            for (int s = 0; s < 8; ++s) {
                ulonglong2 h2 = ((ulonglong2*)hsm)[s*16 + k4];
                acc[s] = fma2(wa, h2.x, acc[s]);
                acc[s] = fma2(wb, h2.y, acc[s]);
            }
        }
        #pragma unroll
        for (int s = 0; s < 8; ++s) gts[s*256 + g] = hsum2(acc[s]);
        __syncthreads();
        #pragma unroll
        for (int r = 0; r < 2; ++r) {
            int u = tid + r*256;
            int s = u >> 6, j = u & 63;
            float i_ = sigf(gts[s*256 + j]);
            float f_ = sigf(gts[s*256 + 64 + j]);
            float gg = tanh_(gts[s*256 + 128 + j]);
            float o_ = sigf(gts[s*256 + 192 + j]);
            float c = f_*csm[u] + i_*gg;
            csm[u] = c;
            hsm[u] = o_*tanh_(c);
        }
        __syncthreads();
    }

    const int off = 300 + (dir ? 0 : 64);
    #pragma unroll
    for (int r = 0; r < 2; ++r) {
        int u = tid + r*256;
        int s = u >> 6, j = u & 63;
        g_x[(seq0 + s)*XS_ + off + j] = hsm[u];
    }
    if (dir == 1) {
        for (int u = tid; u < 600; u += 256) {
            int s = u / 75, f4 = u % 75;
            int row = seq0 + s;
            int w = sentence[row];
            ((float4*)&g_x[row*XS_])[f4] = ((const float4*)&emb[w*EMB_])[f4];
        }
        if (tid < 8)
            *(float4*)&g_x[(seq0 + tid)*XS_ + 428] = make_float4(0.f,0.f,0.f,0.f);
    }
}

// ---- xg[dir] = x @ Wih^T (128x64 tile), f32x2 over row-pairs (bit-exact) ----
__global__ void wih_gemm_kernel(const float* __restrict__ Wf,
                                const float* __restrict__ Wb)
{
    __shared__ __align__(16) float As[16*132];
    __shared__ __align__(16) float Bs[16*68];
    const int dir = blockIdx.z;
    const float* W = dir ? Wb : Wf;
    float* Cout = g_xg[dir];
    const int m0 = blockIdx.x*128, n0 = blockIdx.y*64;
    const int tid = threadIdx.x;
    const int tm = tid >> 4, tn = tid & 15;
    const int ar = tid >> 1, ac = tid & 1;
    const int br = tid >> 2, bc = tid & 3;

    ull acc2[4][4];
    #pragma unroll
    for (int i = 0; i < 4; ++i)
        #pragma unroll
        for (int j = 0; j < 4; ++j) acc2[i][j] = 0ull;

    for (int k0 = 0; k0 < XS_; k0 += 16) {
        const float4* arow = (const float4*)&g_x[(m0+ar)*XS_ + k0];
        float4 a0 = arow[ac*2];
        float4 a1 = arow[ac*2+1];
        int kk = k0 + bc*4;
        float4 bv = make_float4(0.f,0.f,0.f,0.f);
        if (kk + 4 <= EIN_) bv = *(const float4*)&W[(n0+br)*EIN_ + kk];
        As[(ac*8+0)*132+ar]=a0.x; As[(ac*8+1)*132+ar]=a0.y;
        As[(ac*8+2)*132+ar]=a0.z; As[(ac*8+3)*132+ar]=a0.w;
        As[(ac*8+4)*132+ar]=a1.x; As[(ac*8+5)*132+ar]=a1.y;
        As[(ac*8+6)*132+ar]=a1.z; As[(ac*8+7)*132+ar]=a1.w;
        Bs[(bc*4+0)*68+br]=bv.x; Bs[(bc*4+1)*68+br]=bv.y;
        Bs[(bc*4+2)*68+br]=bv.z; Bs[(bc*4+3)*68+br]=bv.w;
        __syncthreads();
        #pragma unroll
        for (int k = 0; k < 16; ++k) {
            ulonglong2 aA = ((const ulonglong2*)&As[k*132])[tm*2];
            ulonglong2 aB = ((const ulonglong2*)&As[k*132])[tm*2+1];
            float4 b4 = ((float4*)&Bs[k*68])[tn];
            ull bd0 = dup2(b4.x), bd1 = dup2(b4.y), bd2 = dup2(b4.z), bd3 = dup2(b4.w);
            acc2[0][0]=fma2(aA.x,bd0,acc2[0][0]); acc2[0][1]=fma2(aA.x,bd1,acc2[0][1]);
            acc2[0][2]=fma2(aA.x,bd2,acc2[0][2]); acc2[0][3]=fma2(aA.x,bd3,acc2[0][3]);
            acc2[1][0]=fma2(aA.y,bd0,acc2[1][0]); acc2[1][1]=fma2(aA.y,bd1,acc2[1][1]);
            acc2[1][2]=fma2(aA.y,bd2,acc2[1][2]); acc2[1][3]=fma2(aA.y,bd3,acc2[1][3]);
            acc2[2][0]=fma2(aB.x,bd0,acc2[2][0]); acc2[2][1]=fma2(aB.x,bd1,acc2[2][1]);
            acc2[2][2]=fma2(aB.x,bd2,acc2[2][2]); acc2[2][3]=fma2(aB.x,bd3,acc2[2][3]);
            acc2[3][0]=fma2(aB.y,bd0,acc2[3][0]); acc2[3][1]=fma2(aB.y,bd1,acc2[3][1]);
            acc2[3][2]=fma2(aB.y,bd2,acc2[3][2]); acc2[3][3]=fma2(aB.y,bd3,acc2[3][3]);
        }
        __syncthreads();
    }
    #pragma unroll
    for (int i2 = 0; i2 < 4; ++i2) {
        float2 p0 = unpack2(acc2[i2][0]);
        float2 p1 = unpack2(acc2[i2][1]);
        float2 p2 = unpack2(acc2[i2][2]);
        float2 p3 = unpack2(acc2[i2][3]);
        *(float4*)&Cout[(m0 + tm*8 + 2*i2    )*1024 + n0 + tn*4] =
            make_float4(p0.x, p1.x, p2.x, p3.x);
        *(float4*)&Cout[(m0 + tm*8 + 2*i2 + 1)*1024 + n0 + tn*4] =
            make_float4(p0.y, p1.y, p2.y, p3.y);
    }
}

// ---- word BiLSTM v7: clusters of 8, bulk DSMEM h-exchange, f32x2 FMA ----
// ring layout: [buf(4)][c(8)][b(4)][j(32)]  (one contiguous 512B block per CTA)
__global__ void __launch_bounds__(256, 1) __cluster_dims__(8, 1, 1)
word_lstm_kernel(
    const float* __restrict__ Whh_f, const float* __restrict__ Whh_b,
    const float* __restrict__ bih_f, const float* __restrict__ bhh_f,
    const float* __restrict__ bih_b, const float* __restrict__ bhh_b)
{
    // blob layout (bytes):
    // [0,16384)      ring: float[4][8][4][32]
    // [16384,16400)  mbar[2]
    // [16400,16912)  staging: float[4][32] (this CTA's h block)
    // [16912,21008)  red: float[2][4][128]
    // [21008,21520)  bias: float[128]
    __shared__ __align__(16) unsigned char blob[21520];
    float* ring    = (float*)blob;
    float* stage   = (float*)(blob + 16400);
    float* red     = (float*)(blob + 16912);
    float* bias_s  = (float*)(blob + 21008);
    const uint32_t blob_a  = smem_u32(blob);
    const uint32_t mbar_a  = blob_a + 16384u;
    const uint32_t stage_a = blob_a + 16400u;

    const int tid = threadIdx.x;
    const int dir = blockIdx.x >> 6;
    const int grp = (blockIdx.x >> 3) & 7;
    const int c   = blockIdx.x & 7;     // == cluster rank
    const int u0  = c*32;
    const float* Whh = dir ? Whh_b : Whh_f;
    const float* bi  = dir ? bih_b : bih_f;
    const float* bh  = dir ? bhh_b : bhh_f;
    const float* xg  = g_xg[dir];

    uint32_t rblob[8];
    #pragma unroll
    for (int rr = 0; rr < 8; ++rr)
        asm("mapa.shared::cluster.u32 %0, %1, %2;" : "=r"(rblob[rr]) : "r"(blob_a), "r"(rr));

    const int r = tid & 127, khalf = tid >> 7;
    const int q = r >> 5, j = r & 31;
    const int grow = q*256 + u0 + j;

    // weights as packed k-pairs (k enumerated linearly — matches ring order)
    ull w2[64];
    #pragma unroll
    for (int i = 0; i < 32; ++i)
        ((ulonglong2*)w2)[i] = ((const ulonglong2*)&Whh[grow*256 + khalf*128])[i];
    if (khalf == 0) bias_s[r] = bi[grow] + bh[grow];

    const int aj = tid & 31;
    const int au = u0 + aj;
    const int abg = grp*4 + (tid >> 5);             // global batch (tid<128)
    float c_reg = 0.f;

    ((float4*)(ring + 3*1024))[tid] = make_float4(0.f,0.f,0.f,0.f);  // buf3 = h0 = 0
    if (tid == 0) { mbar_init(mbar_a, 1u); mbar_init(mbar_a + 8u, 1u); }
    __syncthreads();
    CLUSTER_SYNC();   // peers' ring/mbar initialized before any bulk copy

    for (int it = 0; it < 256; ++it) {
        const int tcur = dir ? (255 - it) : it;
        const int rbuf = (it + 3) & 3, wbuf = it & 3;

        if (tid == 0)
            mbar_expect_tx(mbar_a + (uint32_t)(it & 1)*8u, 4096u);

        float xv0=0.f, xv1=0.f, xv2=0.f, xv3=0.f;
        if (tid < 128) {
            const float* xr = &xg[(abg*256 + tcur)*1024 + au];
            xv0 = xr[0]; xv1 = xr[256]; xv2 = xr[512]; xv3 = xr[768];
        }

        // all threads wait for this step's incoming h (HW-sleep)
        if (it > 0)
            mbar_wait(mbar_a + (uint32_t)((it-1) & 1)*8u, (uint32_t)(((it-1) >> 1) & 1));

        // gates: 4 batch chains; ring[rbuf][c][b][j], k = c*32+j (linear)
        {
            const float* hb = &ring[rbuf*1024 + khalf*512];
            ull A0=0ull, A1=0ull, A2=0ull, A3=0ull;
            #pragma unroll
            for (int cc = 0; cc < 4; ++cc) {
                const ulonglong2* h0 = (const ulonglong2*)&hb[cc*128 + 0*32];
                const ulonglong2* h1 = (const ulonglong2*)&hb[cc*128 + 1*32];
                const ulonglong2* h2 = (const ulonglong2*)&hb[cc*128 + 2*32];
                const ulonglong2* h3 = (const ulonglong2*)&hb[cc*128 + 3*32];
                #pragma unroll
                for (int k4 = 0; k4 < 8; ++k4) {
                    ull wa = w2[cc*16 + k4*2], wb = w2[cc*16 + k4*2+1];
                    ulonglong2 v0 = h0[k4], v1 = h1[k4], v2 = h2[k4], v3 = h3[k4];
                    A0 = fma2(wa, v0.x, A0); A0 = fma2(wb, v0.y, A0);
                    A1 = fma2(wa, v1.x, A1); A1 = fma2(wb, v1.y, A1);
                    A2 = fma2(wa, v2.x, A2); A2 = fma2(wb, v2.y, A2);
                    A3 = fma2(wa, v3.x, A3); A3 = fma2(wb, v3.y, A3);
                }
            }
            red[khalf*512 + 0*128 + r] = hsum2(A0);
            red[khalf*512 + 1*128 + r] = hsum2(A1);
            red[khalf*512 + 2*128 + r] = hsum2(A2);
            red[khalf*512 + 3*128 + r] = hsum2(A3);
        }
        __syncthreads();

        if (tid < 128) {
            const int b = tid >> 5;
            float s0 = bias_s[0*32 + aj] + xv0 + red[b*128 + 0*32 + aj] + red[512 + b*128 + 0*32 + aj];
            float s1 = bias_s[1*32 + aj] + xv1 + red[b*128 + 1*32 + aj] + red[512 + b*128 + 1*32 + aj];
            float s2 = bias_s[2*32 + aj] + xv2 + red[b*128 + 2*32 + aj] + red[512 + b*128 + 2*32 + aj];
            float s3 = bias_s[3*32 + aj] + xv3 + red[b*128 + 3*32 + aj] + red[512 + b*128 + 3*32 + aj];
            float i_ = sigf(s0), f_ = sigf(s1), gg = tanh_(s2), o_ = sigf(s3);
            float cc = f_*c_reg + i_*gg;
            c_reg = cc;
            float h = o_*tanh_(cc);
            g_hs[(abg*256 + tcur)*512 + dir*256 + au] = h;   // for proj
            stage[b*32 + aj] = h;                            // local staging
        }
        __syncthreads();   // staging complete; red consumed

        if (tid < 8) {
            asm volatile("fence.proxy.async.shared::cta;" ::: "memory");
            uint32_t dst = rblob[tid] + (uint32_t)(wbuf*4096 + c*512);
            uint32_t mb  = rblob[tid] + 16384u + (uint32_t)(it & 1)*8u;
            asm volatile(
                "cp.async.bulk.shared::cluster.shared::cta.mbarrier::complete_tx::bytes "
                "[%0], [%1], %2, [%3];"
                :: "r"(dst), "r"(stage_a), "r"(512), "r"(mb) : "memory");
        }
    }
    CLUSTER_SYNC();   // no CTA exits while peers' copies may be in flight
}

// ---- feats = hs @ projW^T + b ----
__global__ void proj_kernel(const float* __restrict__ projW,
                            const float* __restrict__ projb)
{
    extern __shared__ float sm[];
    float* pw = sm;               // [512][33]
    float* hr = pw + 512*33;      // [8][512]
    const int tid = threadIdx.x;
    for (int u = tid; u < 32*512; u += 256) {
        int l = u >> 9, k = u & 511;
        pw[k*33 + l] = projW[u];
    }
    int row0 = blockIdx.x*8;
    for (int u = tid; u < 1024; u += 256)
        ((float4*)hr)[u] = ((const float4*)&g_hs[row0*512])[u];
    __syncthreads();

    int r = tid >> 5, l = tid & 31;
    float acc = projb[l];
    #pragma unroll 4
    for (int k4 = 0; k4 < 128; ++k4) {
        float4 h4 = ((float4*)hr)[r*128 + k4];
        acc += h4.x*pw[(k4*4+0)*33 + l] + h4.y*pw[(k4*4+1)*33 + l]
             + h4.z*pw[(k4*4+2)*33 + l] + h4.w*pw[(k4*4+3)*33 + l];
    }
    g_feats[(row0 + r)*32 + l] = acc;
}

// ---- viterbi: one warp per batch element ----
__global__ void viterbi_kernel(const float* __restrict__ trans, float* __restrict__ out)
{
    __shared__ float fv[32];
    __shared__ float tr[32*33];
    __shared__ unsigned char bpv[256*32];
    const int l = threadIdx.x, b = blockIdx.x;
    for (int u = l; u < 1024; u += 32) tr[(u>>5)*33 + (u&31)] = trans[u];
    fv[l] = -10000.0f;
    __syncwarp();

    for (int t = 0; t < 256; ++t) {
        float m = -1e30f; int am = 0;
        #pragma unroll
        for (int pi = 0; pi < 32; ++pi) {
            float s = fv[pi] + tr[l*33 + pi];
            if (s > m) { m = s; am = pi; }
        }
        bpv[t*32 + l] = (unsigned char)am;
        float nf = m + g_feats[(b*256 + t)*32 + l];
        __syncwarp();
        fv[l] = nf;
        __syncwarp();
    }
    if (l == 0) {
        float bm = fv[0]; int bt = 0;
        for (int pi = 1; pi < 32; ++pi) if (fv[pi] > bm) { bm = fv[pi]; bt = pi; }
        out[b] = bm;
        int tag = bt;
        for (int t = 255; t >= 0; --t) {
            out[32 + b*256 + t] = (float)tag;
            tag = (int)bpv[t*32 + tag];
        }
    }
}

extern "C" void kernel_launch(void* const* d_in, const int* in_sizes, int n_in,
                              void* d_out, int out_size)
{
    const int* sent = (const int*)d_in[0];
    const int* cseq = (const int*)d_in[1];
    const float* const* F = (const float* const*)(d_in + 2);
    float* out = (float*)d_out;

    cudaFuncSetAttribute(char_rec_kernel,  cudaFuncAttributeMaxDynamicSharedMemorySize, 100000);
    cudaFuncSetAttribute(proj_kernel,      cudaFuncAttributeMaxDynamicSharedMemorySize, 90000);

    ctab_kernel<<<dim3(CV_, 2), 256>>>(F[1], F[2], F[6]);
    char_rec_kernel<<<dim3(NROW/8, 2), 256, 79104>>>(
        F[3], F[4], F[5], F[7], F[8], F[9], cseq, sent, F[0]);
    wih_gemm_kernel<<<dim3(NROW/128, 1024/64, 2), 256>>>(F[10], F[14]);
    word_lstm_kernel<<<128, 256>>>(F[11], F[15], F[12], F[13], F[16], F[17]);
    proj_kernel<<<NROW/8, 256, 83968>>>(F[18], F[19]);
    viterbi_kernel<<<BB, 32>>>(F[20], out);
}

// round 15
// speedup vs baseline: 1.0174x; 1.0174x over previous
#include <cuda_runtime.h>
#include <cstdint>

#define BB 32
#define TT_ 256
#define CHL 16
#define CE_ 64
#define HC_ 64
#define HW_ 256
#define EMB_ 300
#define EIN_ 428
#define XS_ 432
#define LL_ 32
#define CV_ 128
#define NROW (BB*TT_)

typedef unsigned long long ull;

__device__ float g_x[NROW*XS_];
__device__ float g_xg[2][NROW*1024];          // natural: [dir][m][gate]
__device__ float g_ctab[2][CV_*256];          // char input-projection table
__device__ float g_hs[NROW*512];              // [row][dir*256+k]  (for proj)
__device__ float g_feats[NROW*LL_];

__device__ __forceinline__ float sigf(float x) { return 1.0f/(1.0f+__expf(-x)); }
__device__ __forceinline__ float tanh_(float x) {
    x = fmaxf(x, -43.0f);
    float e = __expf(-2.0f*x);
    return (1.0f - e)/(1.0f + e);
}

// ---- packed f32x2 helpers (sm_100+) ----
__device__ __forceinline__ ull fma2(ull a, ull b, ull c) {
    ull d;
    asm("fma.rn.f32x2 %0, %1, %2, %3;" : "=l"(d) : "l"(a), "l"(b), "l"(c));
    return d;
}
__device__ __forceinline__ ull dup2(float x) {
    ull d;
    asm("mov.b64 %0, {%1, %1};" : "=l"(d) : "f"(x));
    return d;
}
__device__ __forceinline__ float2 unpack2(ull v) {
    float2 r;
    asm("mov.b64 {%0, %1}, %2;" : "=f"(r.x), "=f"(r.y) : "l"(v));
    return r;
}
__device__ __forceinline__ float hsum2(ull v) {
    float2 r = unpack2(v);
    return r.x + r.y;
}
__device__ __forceinline__ ull pack2(float lo, float hi) {
    ull d;
    asm("mov.b64 %0, {%1, %2};" : "=l"(d) : "f"(lo), "f"(hi));
    return d;
}

__device__ __forceinline__ uint32_t smem_u32(const void* p) {
    uint32_t a;
    asm("{ .reg .u64 t; cvta.to.shared.u64 t, %1; cvt.u32.u64 %0, t; }"
        : "=r"(a) : "l"(p));
    return a;
}
#define CLUSTER_SYNC() do { \
    asm volatile("barrier.cluster.arrive.aligned;" ::: "memory"); \
    asm volatile("barrier.cluster.wait.aligned;" ::: "memory"); \
} while(0)

__device__ __forceinline__ void mbar_init(uint32_t addr, uint32_t cnt) {
    asm volatile("mbarrier.init.shared.b64 [%0], %1;" :: "r"(addr), "r"(cnt) : "memory");
}
__device__ __forceinline__ void mbar_expect_tx(uint32_t addr, uint32_t bytes) {
    asm volatile("mbarrier.arrive.expect_tx.shared.b64 _, [%0], %1;"
                 :: "r"(addr), "r"(bytes) : "memory");
}
__device__ __forceinline__ void mbar_wait(uint32_t addr, uint32_t parity) {
    asm volatile(
        "{\n\t.reg .pred P;\n\t"
        "W_%=:\n\t"
        "mbarrier.try_wait.parity.acquire.cta.shared::cta.b64 P, [%0], %1, 0x989680;\n\t"
        "@P bra D_%=;\n\t"
        "bra W_%=;\n\t"
        "D_%=:\n\t}"
        :: "r"(addr), "r"(parity) : "memory");
}

// ---- ctab[dir][c][g] = char_emb[c] . Wih[g] ----
__global__ void ctab_kernel(const float* __restrict__ char_emb,
                            const float* __restrict__ Wf,
                            const float* __restrict__ Wb)
{
    __shared__ float e[64];
    const int c = blockIdx.x, dir = blockIdx.y;
    const float* W = dir ? Wb : Wf;
    const int g = threadIdx.x;
    if (g < 64) e[g] = char_emb[c*64 + g];
    __syncthreads();
    float s = 0.f;
    #pragma unroll
    for (int k = 0; k < 64; ++k) s += e[k]*W[g*64 + k];
    g_ctab[dir][c*256 + g] = s;
}

// ---- char recurrence + x assembly: 8 seqs/block, dir = blockIdx.y, f32x2 ----
__global__ void char_rec_kernel(
    const float* __restrict__ Whh_f, const float* __restrict__ bih_f, const float* __restrict__ bhh_f,
    const float* __restrict__ Whh_b, const float* __restrict__ bih_b, const float* __restrict__ bhh_b,
    const int* __restrict__ cseq,
    const int* __restrict__ sentence, const float* __restrict__ emb)
{
    extern __shared__ __align__(16) unsigned char smraw[];
    const int P = 257;
    ull*   WhhP = (ull*)smraw;                 // [32 k2][257]
    float* bsum = (float*)(WhhP + 32*P);       // [256]
    float* hsm  = bsum + 256;                  // [8][64]
    float* csm  = hsm + 512;                   // [8][64]
    float* gts  = csm + 512;                   // [8][256]
    __shared__ int cid[128];

    const int dir = blockIdx.y;
    const float* Whh = dir ? Whh_b : Whh_f;
    const float* bih = dir ? bih_b : bih_f;
    const float* bhh = dir ? bhh_b : bhh_f;
    const float* tab = g_ctab[dir];
    const int tid = threadIdx.x;
    const int seq0 = blockIdx.x*8;

    const ull* Wp = (const ull*)Whh;           // [256][32]
    for (int u = tid; u < 256*32; u += 256) {
        int g = u >> 5, k2 = u & 31;
        WhhP[k2*P + g] = Wp[u];
    }
    bsum[tid] = bih[tid] + bhh[tid];
    if (tid < 128) cid[tid] = cseq[seq0*CHL + tid];
    for (int u = tid; u < 512; u += 256) { hsm[u] = 0.f; csm[u] = 0.f; }
    __syncthreads();

    const int g = tid;
    for (int step = 0; step < 16; ++step) {
        int tcur = dir ? (15 - step) : step;
        ull acc[8];
        #pragma unroll
        for (int s = 0; s < 8; ++s)
            acc[s] = pack2(bsum[g] + tab[cid[s*16 + tcur]*256 + g], 0.f);
        #pragma unroll 4
        for (int k4 = 0; k4 < 16; ++k4) {
            ull wa = WhhP[(2*k4)*P + g];
            ull wb = WhhP[(2*k4+1)*P + g];
            #pragma unroll
            for (int s = 0; s < 8; ++s) {
                ulonglong2 h2 = ((ulonglong2*)hsm)[s*16 + k4];
                acc[s] = fma2(wa, h2.x, acc[s]);
                acc[s] = fma2(wb, h2.y, acc[s]);
            }
        }
        #pragma unroll
        for (int s = 0; s < 8; ++s) gts[s*256 + g] = hsum2(acc[s]);
        __syncthreads();
        #pragma unroll
        for (int r = 0; r < 2; ++r) {
            int u = tid + r*256;
            int s = u >> 6, j = u & 63;
            float i_ = sigf(gts[s*256 + j]);
            float f_ = sigf(gts[s*256 + 64 + j]);
            float gg = tanh_(gts[s*256 + 128 + j]);
            float o_ = sigf(gts[s*256 + 192 + j]);
            float c = f_*csm[u] + i_*gg;
            csm[u] = c;
            hsm[u] = o_*tanh_(c);
        }
        __syncthreads();
    }

    const int off = 300 + (dir ? 0 : 64);
    #pragma unroll
    for (int r = 0; r < 2; ++r) {
        int u = tid + r*256;
        int s = u >> 6, j = u & 63;
        g_x[(seq0 + s)*XS_ + off + j] = hsm[u];
    }
    if (dir == 1) {
        for (int u = tid; u < 600; u += 256) {
            int s = u / 75, f4 = u % 75;
            int row = seq0 + s;
            int w = sentence[row];
            ((float4*)&g_x[row*XS_])[f4] = ((const float4*)&emb[w*EMB_])[f4];
        }
        if (tid < 8)
            *(float4*)&g_x[(seq0 + tid)*XS_ + 428] = make_float4(0.f,0.f,0.f,0.f);
    }
}

// ---- xg[dir] = x @ Wih^T: 128x128 tile, 8x8 per thread, f32x2 (bit-exact) ----
__global__ void wih_gemm_kernel(const float* __restrict__ Wf,
                                const float* __restrict__ Wb)
{
    __shared__ __align__(16) float As[16*132];
    __shared__ __align__(16) float Bs[16*132];
    const int dir = blockIdx.z;
    const float* W = dir ? Wb : Wf;
    float* Cout = g_xg[dir];
    const int m0 = blockIdx.x*128, n0 = blockIdx.y*128;
    const int tid = threadIdx.x;
    const int tm = tid >> 4, tn = tid & 15;
    const int lr = tid >> 1, lc = tid & 1;   // loader: row 0..127, k-half 0/1

    ull acc2[4][8];   // [row-pair][col]
    #pragma unroll
    for (int i = 0; i < 4; ++i)
        #pragma unroll
        for (int j = 0; j < 8; ++j) acc2[i][j] = 0ull;

    for (int k0 = 0; k0 < XS_; k0 += 16) {
        const float4* ar4 = (const float4*)&g_x[(m0+lr)*XS_ + k0 + lc*8];
        float4 a0 = ar4[0];
        float4 a1 = ar4[1];
        int kk = k0 + lc*8;
        float4 b0 = make_float4(0.f,0.f,0.f,0.f);
        float4 b1 = make_float4(0.f,0.f,0.f,0.f);
        if (kk + 4 <= EIN_) b0 = *(const float4*)&W[(n0+lr)*EIN_ + kk];
        if (kk + 8 <= EIN_) b1 = *(const float4*)&W[(n0+lr)*EIN_ + kk + 4];
        As[(lc*8+0)*132+lr]=a0.x; As[(lc*8+1)*132+lr]=a0.y;
        As[(lc*8+2)*132+lr]=a0.z; As[(lc*8+3)*132+lr]=a0.w;
        As[(lc*8+4)*132+lr]=a1.x; As[(lc*8+5)*132+lr]=a1.y;
        As[(lc*8+6)*132+lr]=a1.z; As[(lc*8+7)*132+lr]=a1.w;
        Bs[(lc*8+0)*132+lr]=b0.x; Bs[(lc*8+1)*132+lr]=b0.y;
        Bs[(lc*8+2)*132+lr]=b0.z; Bs[(lc*8+3)*132+lr]=b0.w;
        Bs[(lc*8+4)*132+lr]=b1.x; Bs[(lc*8+5)*132+lr]=b1.y;
        Bs[(lc*8+6)*132+lr]=b1.z; Bs[(lc*8+7)*132+lr]=b1.w;
        __syncthreads();
        #pragma unroll
        for (int k = 0; k < 16; ++k) {
            ulonglong2 aA = ((const ulonglong2*)&As[k*132])[tm*2];     // rows (8tm..+3) pairs
            ulonglong2 aB = ((const ulonglong2*)&As[k*132])[tm*2+1];   // rows (+4..+7) pairs
            float4 bv0 = *(const float4*)&Bs[k*132 + tn*8];
            float4 bv1 = *(const float4*)&Bs[k*132 + tn*8 + 4];
            ull bd0 = dup2(bv0.x), bd1 = dup2(bv0.y), bd2 = dup2(bv0.z), bd3 = dup2(bv0.w);
            ull bd4 = dup2(bv1.x), bd5 = dup2(bv1.y), bd6 = dup2(bv1.z), bd7 = dup2(bv1.w);
            acc2[0][0]=fma2(aA.x,bd0,acc2[0][0]); acc2[0][1]=fma2(aA.x,bd1,acc2[0][1]);
            acc2[0][2]=fma2(aA.x,bd2,acc2[0][2]); acc2[0][3]=fma2(aA.x,bd3,acc2[0][3]);
            acc2[0][4]=fma2(aA.x,bd4,acc2[0][4]); acc2[0][5]=fma2(aA.x,bd5,acc2[0][5]);
            acc2[0][6]=fma2(aA.x,bd6,acc2[0][6]); acc2[0][7]=fma2(aA.x,bd7,acc2[0][7]);
            acc2[1][0]=fma2(aA.y,bd0,acc2[1][0]); acc2[1][1]=fma2(aA.y,bd1,acc2[1][1]);
            acc2[1][2]=fma2(aA.y,bd2,acc2[1][2]); acc2[1][3]=fma2(aA.y,bd3,acc2[1][3]);
            acc2[1][4]=fma2(aA.y,bd4,acc2[1][4]); acc2[1][5]=fma2(aA.y,bd5,acc2[1][5]);
            acc2[1][6]=fma2(aA.y,bd6,acc2[1][6]); acc2[1][7]=fma2(aA.y,bd7,acc2[1][7]);
            acc2[2][0]=fma2(aB.x,bd0,acc2[2][0]); acc2[2][1]=fma2(aB.x,bd1,acc2[2][1]);
            acc2[2][2]=fma2(aB.x,bd2,acc2[2][2]); acc2[2][3]=fma2(aB.x,bd3,acc2[2][3]);
            acc2[2][4]=fma2(aB.x,bd4,acc2[2][4]); acc2[2][5]=fma2(aB.x,bd5,acc2[2][5]);
            acc2[2][6]=fma2(aB.x,bd6,acc2[2][6]); acc2[2][7]=fma2(aB.x,bd7,acc2[2][7]);
            acc2[3][0]=fma2(aB.y,bd0,acc2[3][0]); acc2[3][1]=fma2(aB.y,bd1,acc2[3][1]);
            acc2[3][2]=fma2(aB.y,bd2,acc2[3][2]); acc2[3][3]=fma2(aB.y,bd3,acc2[3][3]);
            acc2[3][4]=fma2(aB.y,bd4,acc2[3][4]); acc2[3][5]=fma2(aB.y,bd5,acc2[3][5]);
            acc2[3][6]=fma2(aB.y,bd6,acc2[3][6]); acc2[3][7]=fma2(aB.y,bd7,acc2[3][7]);
        }
        __syncthreads();
    }
    #pragma unroll
    for (int i2 = 0; i2 < 4; ++i2) {
        float2 p0 = unpack2(acc2[i2][0]), p1 = unpack2(acc2[i2][1]);
        float2 p2 = unpack2(acc2[i2][2]), p3 = unpack2(acc2[i2][3]);
        float2 p4 = unpack2(acc2[i2][4]), p5 = unpack2(acc2[i2][5]);
        float2 p6 = unpack2(acc2[i2][6]), p7 = unpack2(acc2[i2][7]);
        float* r0 = &Cout[(m0 + tm*8 + 2*i2    )*1024 + n0 + tn*8];
        float* r1 = &Cout[(m0 + tm*8 + 2*i2 + 1)*1024 + n0 + tn*8];
        *(float4*)r0       = make_float4(p0.x, p1.x, p2.x, p3.x);
        *(float4*)(r0 + 4) = make_float4(p4.x, p5.x, p6.x, p7.x);
        *(float4*)r1       = make_float4(p0.y, p1.y, p2.y, p3.y);
        *(float4*)(r1 + 4) = make_float4(p4.y, p5.y, p6.y, p7.y);
    }
}

// ---- word BiLSTM (R13 version): clusters of 8, st.async mbarrier ring, f32x2 ----
__global__ void __launch_bounds__(256, 1) __cluster_dims__(8, 1, 1)
word_lstm_kernel(
    const float* __restrict__ Whh_f, const float* __restrict__ Whh_b,
    const float* __restrict__ bih_f, const float* __restrict__ bhh_f,
    const float* __restrict__ bih_b, const float* __restrict__ bhh_b)
{
    // blob: [0,16384) ring f[4][1024]; [16384,16400) mbar[2];
    //       [16400,20496) red f[2][4][128]; [20496,21008) bias f[128]
    __shared__ __align__(16) unsigned char blob[21008];
    float* ring    = (float*)blob;
    float* red     = (float*)(blob + 16400);
    float* bias_s  = (float*)(blob + 20496);
    const uint32_t blob_a = smem_u32(blob);
    const uint32_t mbar_a = blob_a + 16384u;

    const int tid = threadIdx.x;
    const int dir = blockIdx.x >> 6;
    const int grp = (blockIdx.x >> 3) & 7;
    const int c   = blockIdx.x & 7;
    const int u0  = c*32;
    const float* Whh = dir ? Whh_b : Whh_f;
    const float* bi  = dir ? bih_b : bih_f;
    const float* bh  = dir ? bhh_b : bhh_f;
    const float* xg  = g_xg[dir];

    uint32_t rblob[8];
    #pragma unroll
    for (int rr = 0; rr < 8; ++rr)
        asm("mapa.shared::cluster.u32 %0, %1, %2;" : "=r"(rblob[rr]) : "r"(blob_a), "r"(rr));

    const int r = tid & 127, khalf = tid >> 7;
    const int q = r >> 5, j = r & 31;
    const int grow = q*256 + u0 + j;

    ull w2[64];
    #pragma unroll
    for (int i = 0; i < 32; ++i)
        ((ulonglong2*)w2)[i] = ((const ulonglong2*)&Whh[grow*256 + khalf*128])[i];
    if (khalf == 0) bias_s[r] = bi[grow] + bh[grow];

    const int aj = tid & 31;
    const int au = u0 + aj;
    const int abg = grp*4 + (tid >> 5);
    float c_reg = 0.f;

    ((float4*)(ring + 3*1024))[tid] = make_float4(0.f,0.f,0.f,0.f);
    if (tid == 0) { mbar_init(mbar_a, 1u); mbar_init(mbar_a + 8u, 1u); }
    __syncthreads();
    CLUSTER_SYNC();

    for (int it = 0; it < 256; ++it) {
        const int tcur = dir ? (255 - it) : it;
        const int rbuf = (it + 3) & 3, wbuf = it & 3;

        if (tid == 0)
            mbar_expect_tx(mbar_a + (uint32_t)(it & 1)*8u, 4096u);

        float xv0=0.f, xv1=0.f, xv2=0.f, xv3=0.f;
        if (tid < 128) {
            const float* xr = &xg[(abg*256 + tcur)*1024 + au];
            xv0 = xr[0]; xv1 = xr[256]; xv2 = xr[512]; xv3 = xr[768];
        }

        if (it > 0 && tid == 0)
            mbar_wait(mbar_a + (uint32_t)((it-1) & 1)*8u, (uint32_t)(((it-1) >> 1) & 1));
        __syncthreads();

        {
            const ulonglong2* h0 = (const ulonglong2*)&ring[rbuf*1024 + 0*256 + khalf*128];
            const ulonglong2* h1 = (const ulonglong2*)&ring[rbuf*1024 + 1*256 + khalf*128];
            const ulonglong2* h2 = (const ulonglong2*)&ring[rbuf*1024 + 2*256 + khalf*128];
            const ulonglong2* h3 = (const ulonglong2*)&ring[rbuf*1024 + 3*256 + khalf*128];
            ull A0=0ull, A1=0ull, A2=0ull, A3=0ull;
            #pragma unroll
            for (int k4 = 0; k4 < 32; ++k4) {
                ull wa = w2[k4*2], wb = w2[k4*2+1];
                ulonglong2 v0 = h0[k4], v1 = h1[k4], v2 = h2[k4], v3 = h3[k4];
                A0 = fma2(wa, v0.x, A0); A0 = fma2(wb, v0.y, A0);
                A1 = fma2(wa, v1.x, A1); A1 = fma2(wb, v1.y, A1);
                A2 = fma2(wa, v2.x, A2); A2 = fma2(wb, v2.y, A2);
                A3 = fma2(wa, v3.x, A3); A3 = fma2(wb, v3.y, A3);
            }
            red[khalf*512 + 0*128 + r] = hsum2(A0);
            red[khalf*512 + 1*128 + r] = hsum2(A1);
            red[khalf*512 + 2*128 + r] = hsum2(A2);
            red[khalf*512 + 3*128 + r] = hsum2(A3);
        }
        __syncthreads();

        if (tid < 128) {
            const int b = tid >> 5;
            float s0 = bias_s[0*32 + aj] + xv0 + red[b*128 + 0*32 + aj] + red[512 + b*128 + 0*32 + aj];
            float s1 = bias_s[1*32 + aj] + xv1 + red[b*128 + 1*32 + aj] + red[512 + b*128 + 1*32 + aj];
            float s2 = bias_s[2*32 + aj] + xv2 + red[b*128 + 2*32 + aj] + red[512 + b*128 + 2*32 + aj];
            float s3 = bias_s[3*32 + aj] + xv3 + red[b*128 + 3*32 + aj] + red[512 + b*128 + 3*32 + aj];
            float i_ = sigf(s0), f_ = sigf(s1), gg = tanh_(s2), o_ = sigf(s3);
            float cc = f_*c_reg + i_*gg;
            c_reg = cc;
            float h = o_*tanh_(cc);
            g_hs[(abg*256 + tcur)*512 + dir*256 + au] = h;
            const uint32_t off   = (uint32_t)(wbuf*1024 + b*256 + au)*4u;
            const uint32_t mboff = 16384u + (uint32_t)(it & 1)*8u;
            const uint32_t hv = __float_as_uint(h);
            #pragma unroll
            for (int rr = 0; rr < 8; ++rr) {
                asm volatile(
                    "st.async.shared::cluster.mbarrier::complete_tx::bytes.u32 [%0], %1, [%2];"
                    :: "r"(rblob[rr] + off), "r"(hv), "r"(rblob[rr] + mboff) : "memory");
            }
        }
    }
    CLUSTER_SYNC();
}

// ---- feats = hs @ projW^T + b ----
__global__ void proj_kernel(const float* __restrict__ projW,
                            const float* __restrict__ projb)
{
    extern __shared__ float sm[];
    float* pw = sm;               // [512][33]
    float* hr = pw + 512*33;      // [8][512]
    const int tid = threadIdx.x;
    for (int u = tid; u < 32*512; u += 256) {
        int l = u >> 9, k = u & 511;
        pw[k*33 + l] = projW[u];
    }
    int row0 = blockIdx.x*8;
    for (int u = tid; u < 1024; u += 256)
        ((float4*)hr)[u] = ((const float4*)&g_hs[row0*512])[u];
    __syncthreads();

    int r = tid >> 5, l = tid & 31;
    float acc = projb[l];
    #pragma unroll 4
    for (int k4 = 0; k4 < 128; ++k4) {
        float4 h4 = ((float4*)hr)[r*128 + k4];
        acc += h4.x*pw[(k4*4+0)*33 + l] + h4.y*pw[(k4*4+1)*33 + l]
             + h4.z*pw[(k4*4+2)*33 + l] + h4.w*pw[(k4*4+3)*33 + l];
    }
    g_feats[(row0 + r)*32 + l] = acc;
}

// ---- viterbi: one warp per batch element ----
__global__ void viterbi_kernel(const float* __restrict__ trans, float* __restrict__ out)
{
    __shared__ float fv[32];
    __shared__ float tr[32*33];
    __shared__ unsigned char bpv[256*32];
    const int l = threadIdx.x, b = blockIdx.x;
    for (int u = l; u < 1024; u += 32) tr[(u>>5)*33 + (u&31)] = trans[u];
    fv[l] = -10000.0f;
    __syncwarp();

    for (int t = 0; t < 256; ++t) {
        float m = -1e30f; int am = 0;
        #pragma unroll
        for (int pi = 0; pi < 32; ++pi) {
            float s = fv[pi] + tr[l*33 + pi];
            if (s > m) { m = s; am = pi; }
        }
        bpv[t*32 + l] = (unsigned char)am;
        float nf = m + g_feats[(b*256 + t)*32 + l];
        __syncwarp();
        fv[l] = nf;
        __syncwarp();
    }
    if (l == 0) {
        float bm = fv[0]; int bt = 0;
        for (int pi = 1; pi < 32; ++pi) if (fv[pi] > bm) { bm = fv[pi]; bt = pi; }
        out[b] = bm;
        int tag = bt;
        for (int t = 255; t >= 0; --t) {
            out[32 + b*256 + t] = (float)tag;
            tag = (int)bpv[t*32 + tag];
        }
    }
}

extern "C" void kernel_launch(void* const* d_in, const int* in_sizes, int n_in,
                              void* d_out, int out_size)
{
    const int* sent = (const int*)d_in[0];
    const int* cseq = (const int*)d_in[1];
    const float* const* F = (const float* const*)(d_in + 2);
    float* out = (float*)d_out;

    cudaFuncSetAttribute(char_rec_kernel,  cudaFuncAttributeMaxDynamicSharedMemorySize, 100000);
    cudaFuncSetAttribute(proj_kernel,      cudaFuncAttributeMaxDynamicSharedMemorySize, 90000);

    ctab_kernel<<<dim3(CV_, 2), 256>>>(F[1], F[2], F[6]);
    char_rec_kernel<<<dim3(NROW/8, 2), 256, 79104>>>(
        F[3], F[4], F[5], F[7], F[8], F[9], cseq, sent, F[0]);
    wih_gemm_kernel<<<dim3(NROW/128, 1024/128, 2), 256>>>(F[10], F[14]);
    word_lstm_kernel<<<128, 256>>>(F[11], F[15], F[12], F[13], F[16], F[17]);
    proj_kernel<<<NROW/8, 256, 83968>>>(F[18], F[19]);
    viterbi_kernel<<<BB, 32>>>(F[20], out);
}

// round 16
// speedup vs baseline: 1.1597x; 1.1399x over previous
#include <cuda_runtime.h>
#include <cstdint>

#define BB 32
#define TT_ 256
#define CHL 16
#define CE_ 64
#define HC_ 64
#define HW_ 256
#define EMB_ 300
#define EIN_ 428
#define XS_ 432
#define LL_ 32
#define CV_ 128
#define NROW (BB*TT_)

typedef unsigned long long ull;

__device__ float g_x[NROW*XS_];
__device__ float g_xg[2][NROW*1024];          // natural: [dir][m][gate]
__device__ float g_ctab[2][CV_*256];          // char input-projection table
__device__ float g_hs[NROW*512];              // [row][dir*256+k]  (for proj)
__device__ float g_feats[NROW*LL_];

__device__ __forceinline__ float sigf(float x) {
    return __fdividef(1.0f, 1.0f + __expf(-x));
}
__device__ __forceinline__ float tanh_(float x) {
    x = fmaxf(x, -43.0f);
    float e = __expf(-2.0f*x);
    return __fdividef(1.0f - e, 1.0f + e);
}

// ---- packed f32x2 helpers (sm_100+) ----
__device__ __forceinline__ ull fma2(ull a, ull b, ull c) {
    ull d;
    asm("fma.rn.f32x2 %0, %1, %2, %3;" : "=l"(d) : "l"(a), "l"(b), "l"(c));
    return d;
}
__device__ __forceinline__ ull dup2(float x) {
    ull d;
    asm("mov.b64 %0, {%1, %1};" : "=l"(d) : "f"(x));
    return d;
}
__device__ __forceinline__ float2 unpack2(ull v) {
    float2 r;
    asm("mov.b64 {%0, %1}, %2;" : "=f"(r.x), "=f"(r.y) : "l"(v));
    return r;
}
__device__ __forceinline__ float hsum2(ull v) {
    float2 r = unpack2(v);
    return r.x + r.y;
}
__device__ __forceinline__ ull pack2(float lo, float hi) {
    ull d;
    asm("mov.b64 %0, {%1, %2};" : "=l"(d) : "f"(lo), "f"(hi));
    return d;
}

__device__ __forceinline__ uint32_t smem_u32(const void* p) {
    uint32_t a;
    asm("{ .reg .u64 t; cvta.to.shared.u64 t, %1; cvt.u32.u64 %0, t; }"
        : "=r"(a) : "l"(p));
    return a;
}
#define CLUSTER_SYNC() do { \
    asm volatile("barrier.cluster.arrive.aligned;" ::: "memory"); \
    asm volatile("barrier.cluster.wait.aligned;" ::: "memory"); \
} while(0)

__device__ __forceinline__ void mbar_init(uint32_t addr, uint32_t cnt) {
    asm volatile("mbarrier.init.shared.b64 [%0], %1;" :: "r"(addr), "r"(cnt) : "memory");
}
__device__ __forceinline__ void mbar_expect_tx(uint32_t addr, uint32_t bytes) {
    asm volatile("mbarrier.arrive.expect_tx.shared.b64 _, [%0], %1;"
                 :: "r"(addr), "r"(bytes) : "memory");
}
__device__ __forceinline__ void mbar_wait(uint32_t addr, uint32_t parity) {
    asm volatile(
        "{\n\t.reg .pred P;\n\t"
        "W_%=:\n\t"
        "mbarrier.try_wait.parity.acquire.cta.shared::cta.b64 P, [%0], %1, 0x989680;\n\t"
        "@P bra D_%=;\n\t"
        "bra W_%=;\n\t"
        "D_%=:\n\t}"
        :: "r"(addr), "r"(parity) : "memory");
}

// ---- ctab[dir][c][g] = char_emb[c] . Wih[g] ----
__global__ void ctab_kernel(const float* __restrict__ char_emb,
                            const float* __restrict__ Wf,
                            const float* __restrict__ Wb)
{
    __shared__ float e[64];
    const int c = blockIdx.x, dir = blockIdx.y;
    const float* W = dir ? Wb : Wf;
    const int g = threadIdx.x;
    if (g < 64) e[g] = char_emb[c*64 + g];
    __syncthreads();
    float s = 0.f;
    #pragma unroll
    for (int k = 0; k < 64; ++k) s += e[k]*W[g*64 + k];
    g_ctab[dir][c*256 + g] = s;
}

// ---- char recurrence + x assembly: 8 seqs/block, dir = blockIdx.y, f32x2 ----
__global__ void char_rec_kernel(
    const float* __restrict__ Whh_f, const float* __restrict__ bih_f, const float* __restrict__ bhh_f,
    const float* __restrict__ Whh_b, const float* __restrict__ bih_b, const float* __restrict__ bhh_b,
    const int* __restrict__ cseq,
    const int* __restrict__ sentence, const float* __restrict__ emb)
{
    extern __shared__ __align__(16) unsigned char smraw[];
    const int P = 257;
    ull*   WhhP = (ull*)smraw;                 // [32 k2][257]
    float* bsum = (float*)(WhhP + 32*P);       // [256]
    float* hsm  = bsum + 256;                  // [8][64]
    float* csm  = hsm + 512;                   // [8][64]
    float* gts  = csm + 512;                   // [8][256]
    __shared__ int cid[128];

    const int dir = blockIdx.y;
    const float* Whh = dir ? Whh_b : Whh_f;
    const float* bih = dir ? bih_b : bih_f;
    const float* bhh = dir ? bhh_b : bhh_f;
    const float* tab = g_ctab[dir];
    const int tid = threadIdx.x;
    const int seq0 = blockIdx.x*8;

    const ull* Wp = (const ull*)Whh;           // [256][32]
    for (int u = tid; u < 256*32; u += 256) {
        int g = u >> 5, k2 = u & 31;
        WhhP[k2*P + g] = Wp[u];
    }
    bsum[tid] = bih[tid] + bhh[tid];
    if (tid < 128) cid[tid] = cseq[seq0*CHL + tid];
    for (int u = tid; u < 512; u += 256) { hsm[u] = 0.f; csm[u] = 0.f; }
    __syncthreads();

    const int g = tid;
    for (int step = 0; step < 16; ++step) {
        int tcur = dir ? (15 - step) : step;
        ull acc[8];
        #pragma unroll
        for (int s = 0; s < 8; ++s)
            acc[s] = pack2(bsum[g] + tab[cid[s*16 + tcur]*256 + g], 0.f);
        #pragma unroll 4
        for (int k4 = 0; k4 < 16; ++k4) {
            ull wa = WhhP[(2*k4)*P + g];
            ull wb = WhhP[(2*k4+1)*P + g];
            #pragma unroll
            for (int s = 0; s < 8; ++s) {
                ulonglong2 h2 = ((ulonglong2*)hsm)[s*16 + k4];
                acc[s] = fma2(wa, h2.x, acc[s]);
                acc[s] = fma2(wb, h2.y, acc[s]);
            }
        }
        #pragma unroll
        for (int s = 0; s < 8; ++s) gts[s*256 + g] = hsum2(acc[s]);
        __syncthreads();
        #pragma unroll
        for (int r = 0; r < 2; ++r) {
            int u = tid + r*256;
            int s = u >> 6, j = u & 63;
            float i_ = sigf(gts[s*256 + j]);
            float f_ = sigf(gts[s*256 + 64 + j]);
            float gg = tanh_(gts[s*256 + 128 + j]);
            float o_ = sigf(gts[s*256 + 192 + j]);
            float c = f_*csm[u] + i_*gg;
            csm[u] = c;
            hsm[u] = o_*tanh_(c);
        }
        __syncthreads();
    }

    const int off = 300 + (dir ? 0 : 64);
    #pragma unroll
    for (int r = 0; r < 2; ++r) {
        int u = tid + r*256;
        int s = u >> 6, j = u & 63;
        g_x[(seq0 + s)*XS_ + off + j] = hsm[u];
    }
    if (dir == 1) {
        for (int u = tid; u < 600; u += 256) {
            int s = u / 75, f4 = u % 75;
            int row = seq0 + s;
            int w = sentence[row];
            ((float4*)&g_x[row*XS_])[f4] = ((const float4*)&emb[w*EMB_])[f4];
        }
        if (tid < 8)
            *(float4*)&g_x[(seq0 + tid)*XS_ + 428] = make_float4(0.f,0.f,0.f,0.f);
    }
}

// ---- xg[dir] = x @ Wih^T: 128x128 tile, 8x8 per thread, f32x2 (bit-exact) ----
__global__ void wih_gemm_kernel(const float* __restrict__ Wf,
                                const float* __restrict__ Wb)
{
    __shared__ __align__(16) float As[16*132];
    __shared__ __align__(16) float Bs[16*132];
    const int dir = blockIdx.z;
    const float* W = dir ? Wb : Wf;
    float* Cout = g_xg[dir];
    const int m0 = blockIdx.x*128, n0 = blockIdx.y*128;
    const int tid = threadIdx.x;
    const int tm = tid >> 4, tn = tid & 15;
    const int lr = tid >> 1, lc = tid & 1;

    ull acc2[4][8];
    #pragma unroll
    for (int i = 0; i < 4; ++i)
        #pragma unroll
        for (int j = 0; j < 8; ++j) acc2[i][j] = 0ull;

    for (int k0 = 0; k0 < XS_; k0 += 16) {
        const float4* ar4 = (const float4*)&g_x[(m0+lr)*XS_ + k0 + lc*8];
        float4 a0 = ar4[0];
        float4 a1 = ar4[1];
        int kk = k0 + lc*8;
        float4 b0 = make_float4(0.f,0.f,0.f,0.f);
        float4 b1 = make_float4(0.f,0.f,0.f,0.f);
        if (kk + 4 <= EIN_) b0 = *(const float4*)&W[(n0+lr)*EIN_ + kk];
        if (kk + 8 <= EIN_) b1 = *(const float4*)&W[(n0+lr)*EIN_ + kk + 4];
        As[(lc*8+0)*132+lr]=a0.x; As[(lc*8+1)*132+lr]=a0.y;
        As[(lc*8+2)*132+lr]=a0.z; As[(lc*8+3)*132+lr]=a0.w;
        As[(lc*8+4)*132+lr]=a1.x; As[(lc*8+5)*132+lr]=a1.y;
        As[(lc*8+6)*132+lr]=a1.z; As[(lc*8+7)*132+lr]=a1.w;
        Bs[(lc*8+0)*132+lr]=b0.x; Bs[(lc*8+1)*132+lr]=b0.y;
        Bs[(lc*8+2)*132+lr]=b0.z; Bs[(lc*8+3)*132+lr]=b0.w;
        Bs[(lc*8+4)*132+lr]=b1.x; Bs[(lc*8+5)*132+lr]=b1.y;
        Bs[(lc*8+6)*132+lr]=b1.z; Bs[(lc*8+7)*132+lr]=b1.w;
        __syncthreads();
        #pragma unroll
        for (int k = 0; k < 16; ++k) {
            ulonglong2 aA = ((const ulonglong2*)&As[k*132])[tm*2];
            ulonglong2 aB = ((const ulonglong2*)&As[k*132])[tm*2+1];
            float4 bv0 = *(const float4*)&Bs[k*132 + tn*8];
            float4 bv1 = *(const float4*)&Bs[k*132 + tn*8 + 4];
            ull bd0 = dup2(bv0.x), bd1 = dup2(bv0.y), bd2 = dup2(bv0.z), bd3 = dup2(bv0.w);
            ull bd4 = dup2(bv1.x), bd5 = dup2(bv1.y), bd6 = dup2(bv1.z), bd7 = dup2(bv1.w);
            acc2[0][0]=fma2(aA.x,bd0,acc2[0][0]); acc2[0][1]=fma2(aA.x,bd1,acc2[0][1]);
            acc2[0][2]=fma2(aA.x,bd2,acc2[0][2]); acc2[0][3]=fma2(aA.x,bd3,acc2[0][3]);
            acc2[0][4]=fma2(aA.x,bd4,acc2[0][4]); acc2[0][5]=fma2(aA.x,bd5,acc2[0][5]);
            acc2[0][6]=fma2(aA.x,bd6,acc2[0][6]); acc2[0][7]=fma2(aA.x,bd7,acc2[0][7]);
            acc2[1][0]=fma2(aA.y,bd0,acc2[1][0]); acc2[1][1]=fma2(aA.y,bd1,acc2[1][1]);
            acc2[1][2]=fma2(aA.y,bd2,acc2[1][2]); acc2[1][3]=fma2(aA.y,bd3,acc2[1][3]);
            acc2[1][4]=fma2(aA.y,bd4,acc2[1][4]); acc2[1][5]=fma2(aA.y,bd5,acc2[1][5]);
            acc2[1][6]=fma2(aA.y,bd6,acc2[1][6]); acc2[1][7]=fma2(aA.y,bd7,acc2[1][7]);
            acc2[2][0]=fma2(aB.x,bd0,acc2[2][0]); acc2[2][1]=fma2(aB.x,bd1,acc2[2][1]);
            acc2[2][2]=fma2(aB.x,bd2,acc2[2][2]); acc2[2][3]=fma2(aB.x,bd3,acc2[2][3]);
            acc2[2][4]=fma2(aB.x,bd4,acc2[2][4]); acc2[2][5]=fma2(aB.x,bd5,acc2[2][5]);
            acc2[2][6]=fma2(aB.x,bd6,acc2[2][6]); acc2[2][7]=fma2(aB.x,bd7,acc2[2][7]);
            acc2[3][0]=fma2(aB.y,bd0,acc2[3][0]); acc2[3][1]=fma2(aB.y,bd1,acc2[3][1]);
            acc2[3][2]=fma2(aB.y,bd2,acc2[3][2]); acc2[3][3]=fma2(aB.y,bd3,acc2[3][3]);
            acc2[3][4]=fma2(aB.y,bd4,acc2[3][4]); acc2[3][5]=fma2(aB.y,bd5,acc2[3][5]);
            acc2[3][6]=fma2(aB.y,bd6,acc2[3][6]); acc2[3][7]=fma2(aB.y,bd7,acc2[3][7]);
        }
        __syncthreads();
    }
    #pragma unroll
    for (int i2 = 0; i2 < 4; ++i2) {
        float2 p0 = unpack2(acc2[i2][0]), p1 = unpack2(acc2[i2][1]);
        float2 p2 = unpack2(acc2[i2][2]), p3 = unpack2(acc2[i2][3]);
        float2 p4 = unpack2(acc2[i2][4]), p5 = unpack2(acc2[i2][5]);
        float2 p6 = unpack2(acc2[i2][6]), p7 = unpack2(acc2[i2][7]);
        float* r0 = &Cout[(m0 + tm*8 + 2*i2    )*1024 + n0 + tn*8];
        float* r1 = &Cout[(m0 + tm*8 + 2*i2 + 1)*1024 + n0 + tn*8];
        *(float4*)r0       = make_float4(p0.x, p1.x, p2.x, p3.x);
        *(float4*)(r0 + 4) = make_float4(p4.x, p5.x, p6.x, p7.x);
        *(float4*)r1       = make_float4(p0.y, p1.y, p2.y, p3.y);
        *(float4*)(r1 + 4) = make_float4(p4.y, p5.y, p6.y, p7.y);
    }
}

// ---- word BiLSTM: clusters of 8, st.async ring, all-thread mbar wait ----
__global__ void __launch_bounds__(256, 1) __cluster_dims__(8, 1, 1)
word_lstm_kernel(
    const float* __restrict__ Whh_f, const float* __restrict__ Whh_b,
    const float* __restrict__ bih_f, const float* __restrict__ bhh_f,
    const float* __restrict__ bih_b, const float* __restrict__ bhh_b)
{
    // blob: [0,16384) ring f[4][1024]; [16384,16400) mbar[2];
    //       [16400,20496) red f[2][4][128]; [20496,21008) bias f[128]
    __shared__ __align__(16) unsigned char blob[21008];
    float* ring    = (float*)blob;
    float* red     = (float*)(blob + 16400);
    float* bias_s  = (float*)(blob + 20496);
    const uint32_t blob_a = smem_u32(blob);
    const uint32_t mbar_a = blob_a + 16384u;

    const int tid = threadIdx.x;
    const int dir = blockIdx.x >> 6;
    const int grp = (blockIdx.x >> 3) & 7;
    const int c   = blockIdx.x & 7;
    const int u0  = c*32;
    const float* Whh = dir ? Whh_b : Whh_f;
    const float* bi  = dir ? bih_b : bih_f;
    const float* bh  = dir ? bhh_b : bhh_f;
    const float* xg  = g_xg[dir];

    uint32_t rblob[8];
    #pragma unroll
    for (int rr = 0; rr < 8; ++rr)
        asm("mapa.shared::cluster.u32 %0, %1, %2;" : "=r"(rblob[rr]) : "r"(blob_a), "r"(rr));

    const int r = tid & 127, khalf = tid >> 7;
    const int q = r >> 5, j = r & 31;
    const int grow = q*256 + u0 + j;

    ull w2[64];
    #pragma unroll
    for (int i = 0; i < 32; ++i)
        ((ulonglong2*)w2)[i] = ((const ulonglong2*)&Whh[grow*256 + khalf*128])[i];
    if (khalf == 0) bias_s[r] = bi[grow] + bh[grow];

    const int aj = tid & 31;
    const int au = u0 + aj;
    const int abg = grp*4 + (tid >> 5);
    float c_reg = 0.f;

    ((float4*)(ring + 3*1024))[tid] = make_float4(0.f,0.f,0.f,0.f);
    if (tid == 0) { mbar_init(mbar_a, 1u); mbar_init(mbar_a + 8u, 1u); }
    __syncthreads();
    CLUSTER_SYNC();

    for (int it = 0; it < 256; ++it) {
        const int tcur = dir ? (255 - it) : it;
        const int rbuf = (it + 3) & 3, wbuf = it & 3;

        if (tid == 0)
            mbar_expect_tx(mbar_a + (uint32_t)(it & 1)*8u, 4096u);

        float xv0=0.f, xv1=0.f, xv2=0.f, xv3=0.f;
        if (tid < 128) {
            const float* xr = &xg[(abg*256 + tcur)*1024 + au];
            xv0 = xr[0]; xv1 = xr[256]; xv2 = xr[512]; xv3 = xr[768];
        }

        // all threads wait (acquire per warp) -> no pre-dot __syncthreads
        if (it > 0)
            mbar_wait(mbar_a + (uint32_t)((it-1) & 1)*8u, (uint32_t)(((it-1) >> 1) & 1));

        {
            const ulonglong2* h0 = (const ulonglong2*)&ring[rbuf*1024 + 0*256 + khalf*128];
            const ulonglong2* h1 = (const ulonglong2*)&ring[rbuf*1024 + 1*256 + khalf*128];
            const ulonglong2* h2 = (const ulonglong2*)&ring[rbuf*1024 + 2*256 + khalf*128];
            const ulonglong2* h3 = (const ulonglong2*)&ring[rbuf*1024 + 3*256 + khalf*128];
            ull A0=0ull, A1=0ull, A2=0ull, A3=0ull;
            #pragma unroll
            for (int k4 = 0; k4 < 32; ++k4) {
                ull wa = w2[k4*2], wb = w2[k4*2+1];
                ulonglong2 v0 = h0[k4], v1 = h1[k4], v2 = h2[k4], v3 = h3[k4];
                A0 = fma2(wa, v0.x, A0); A0 = fma2(wb, v0.y, A0);
                A1 = fma2(wa, v1.x, A1); A1 = fma2(wb, v1.y, A1);
                A2 = fma2(wa, v2.x, A2); A2 = fma2(wb, v2.y, A2);
                A3 = fma2(wa, v3.x, A3); A3 = fma2(wb, v3.y, A3);
            }
            red[khalf*512 + 0*128 + r] = hsum2(A0);
            red[khalf*512 + 1*128 + r] = hsum2(A1);
            red[khalf*512 + 2*128 + r] = hsum2(A2);
            red[khalf*512 + 3*128 + r] = hsum2(A3);
        }
        __syncthreads();

        if (tid < 128) {
            const int b = tid >> 5;
            float s0 = bias_s[0*32 + aj] + xv0 + red[b*128 + 0*32 + aj] + red[512 + b*128 + 0*32 + aj];
            float s1 = bias_s[1*32 + aj] + xv1 + red[b*128 + 1*32 + aj] + red[512 + b*128 + 1*32 + aj];
            float s2 = bias_s[2*32 + aj] + xv2 + red[b*128 + 2*32 + aj] + red[512 + b*128 + 2*32 + aj];
            float s3 = bias_s[3*32 + aj] + xv3 + red[b*128 + 3*32 + aj] + red[512 + b*128 + 3*32 + aj];
            float i_ = sigf(s0), f_ = sigf(s1), gg = tanh_(s2), o_ = sigf(s3);
            float cc = f_*c_reg + i_*gg;
            c_reg = cc;
            float h = o_*tanh_(cc);
            g_hs[(abg*256 + tcur)*512 + dir*256 + au] = h;
            const uint32_t off   = (uint32_t)(wbuf*1024 + b*256 + au)*4u;
            const uint32_t mboff = 16384u + (uint32_t)(it & 1)*8u;
            const uint32_t hv = __float_as_uint(h);
            #pragma unroll
            for (int rr = 0; rr < 8; ++rr) {
                asm volatile(
                    "st.async.shared::cluster.mbarrier::complete_tx::bytes.u32 [%0], %1, [%2];"
                    :: "r"(rblob[rr] + off), "r"(hv), "r"(rblob[rr] + mboff) : "memory");
            }
        }
        // __syncthreads not needed here: red reuse is gated by next step's
        // mbar_wait (our own sends require act reads of red to have completed)
        __syncthreads();
    }
    CLUSTER_SYNC();
}

// ---- feats = hs @ projW^T + b  (16 rows/block, 512 threads) ----
__global__ void proj_kernel(const float* __restrict__ projW,
                            const float* __restrict__ projb)
{
    extern __shared__ float sm[];
    float* pw = sm;               // [512][33]
    float* hr = pw + 512*33;      // [16][512]
    const int tid = threadIdx.x;
    for (int u = tid; u < 32*512; u += 512) {
        int l = u >> 9, k = u & 511;
        pw[k*33 + l] = projW[u];
    }
    int row0 = blockIdx.x*16;
    for (int u = tid; u < 2048; u += 512)
        ((float4*)hr)[u] = ((const float4*)&g_hs[row0*512])[u];
    __syncthreads();

    int r = tid >> 5, l = tid & 31;
    float acc = projb[l];
    #pragma unroll 4
    for (int k4 = 0; k4 < 128; ++k4) {
        float4 h4 = ((float4*)hr)[r*128 + k4];
        acc += h4.x*pw[(k4*4+0)*33 + l] + h4.y*pw[(k4*4+1)*33 + l]
             + h4.z*pw[(k4*4+2)*33 + l] + h4.w*pw[(k4*4+3)*33 + l];
    }
    g_feats[(row0 + r)*32 + l] = acc;
}

// ---- viterbi: one warp per batch element ----
__global__ void viterbi_kernel(const float* __restrict__ trans, float* __restrict__ out)
{
    __shared__ float fv[32];
    __shared__ float tr[32*33];
    __shared__ unsigned char bpv[256*32];
    const int l = threadIdx.x, b = blockIdx.x;
    for (int u = l; u < 1024; u += 32) tr[(u>>5)*33 + (u&31)] = trans[u];
    fv[l] = -10000.0f;
    __syncwarp();

    for (int t = 0; t < 256; ++t) {
        float m = -1e30f; int am = 0;
        #pragma unroll
        for (int pi = 0; pi < 32; ++pi) {
            float s = fv[pi] + tr[l*33 + pi];
            if (s > m) { m = s; am = pi; }
        }
        bpv[t*32 + l] = (unsigned char)am;
        float nf = m + g_feats[(b*256 + t)*32 + l];
        __syncwarp();
        fv[l] = nf;
        __syncwarp();
    }
    if (l == 0) {
        float bm = fv[0]; int bt = 0;
        for (int pi = 1; pi < 32; ++pi) if (fv[pi] > bm) { bm = fv[pi]; bt = pi; }
        out[b] = bm;
        int tag = bt;
        for (int t = 255; t >= 0; --t) {
            out[32 + b*256 + t] = (float)tag;
            tag = (int)bpv[t*32 + tag];
        }
    }
}

extern "C" void kernel_launch(void* const* d_in, const int* in_sizes, int n_in,
                              void* d_out, int out_size)
{
    const int* sent = (const int*)d_in[0];
    const int* cseq = (const int*)d_in[1];
    const float* const* F = (const float* const*)(d_in + 2);
    float* out = (float*)d_out;

    cudaFuncSetAttribute(char_rec_kernel,  cudaFuncAttributeMaxDynamicSharedMemorySize, 100000);
    cudaFuncSetAttribute(proj_kernel,      cudaFuncAttributeMaxDynamicSharedMemorySize, 110000);

    ctab_kernel<<<dim3(CV_, 2), 256>>>(F[1], F[2], F[6]);
    char_rec_kernel<<<dim3(NROW/8, 2), 256, 79104>>>(
        F[3], F[4], F[5], F[7], F[8], F[9], cseq, sent, F[0]);
    wih_gemm_kernel<<<dim3(NROW/128, 1024/128, 2), 256>>>(F[10], F[14]);
    word_lstm_kernel<<<128, 256>>>(F[11], F[15], F[12], F[13], F[16], F[17]);
    // proj smem: 512*33*4 + 16*512*4 = 67584 + 32768 = 100352 B
    proj_kernel<<<NROW/16, 512, 100352>>>(F[18], F[19]);
    viterbi_kernel<<<BB, 32>>>(F[20], out);
}